// round 13
// baseline (speedup 1.0000x reference)
#include <cuda_runtime.h>
#include <cuda_fp16.h>
#include <math.h>
#include <stdint.h>

// ---------------------------------------------------------------------------
// PointSwinBlock on GB300 (sm_103): fp16 mma.sync GEMMs (at legacy-HMMA
// ceiling) + 2-CTA/SM TC window attention + warp-row LN.
// Round 13: LN2 fused into proj epilogue (BN=256 proj variant).
// B=2, N=65536, DIM=256, HEADS=8, HEAD_DIM=32, WS=64, MLP=1024
// ---------------------------------------------------------------------------

#define DIMC   256
#define NTOK   131072
#define NPB    65536
#define HEADS  8
#define HDIM   32
#define WS     64
#define MLPD   1024

__device__ __half g_ln  [(size_t)NTOK * DIMC];
__device__ __half g_qkv [(size_t)NTOK * 768];
__device__ __half g_attn[(size_t)NTOK * DIMC];
__device__ __half g_h   [(size_t)NTOK * MLPD];
__device__ __half g_wqkvT[768 * DIMC];
__device__ __half g_woutT[DIMC * DIMC];
__device__ __half g_w1T  [MLPD * DIMC];
__device__ __half g_w2T  [DIMC * MLPD];

__device__ __forceinline__ uint32_t smem_u32(const void* p) {
    uint32_t a;
    asm("{ .reg .u64 t; cvta.to.shared.u64 t, %1; cvt.u32.u64 %0, t; }"
        : "=r"(a) : "l"(p));
    return a;
}
__device__ __forceinline__ void cpa16(uint32_t dst, const void* src) {
    asm volatile("cp.async.cg.shared.global [%0], [%1], 16;"
                 :: "r"(dst), "l"(src) : "memory");
}
#define CPA_COMMIT() asm volatile("cp.async.commit_group;" ::: "memory")

__device__ __forceinline__ void ldsm4(uint32_t& r0, uint32_t& r1,
                                      uint32_t& r2, uint32_t& r3,
                                      uint32_t addr) {
    asm volatile("ldmatrix.sync.aligned.m8n8.x4.shared.b16 {%0,%1,%2,%3}, [%4];"
                 : "=r"(r0), "=r"(r1), "=r"(r2), "=r"(r3) : "r"(addr));
}
__device__ __forceinline__ void ldsm4t(uint32_t& r0, uint32_t& r1,
                                       uint32_t& r2, uint32_t& r3,
                                       uint32_t addr) {
    asm volatile("ldmatrix.sync.aligned.m8n8.x4.trans.shared.b16 {%0,%1,%2,%3}, [%4];"
                 : "=r"(r0), "=r"(r1), "=r"(r2), "=r"(r3) : "r"(addr));
}
__device__ __forceinline__ void mma_f16(float* d, const uint32_t* a,
                                        const uint32_t* b) {
    asm volatile(
        "mma.sync.aligned.m16n8k16.row.col.f32.f16.f16.f32 "
        "{%0,%1,%2,%3}, {%4,%5,%6,%7}, {%8,%9}, {%0,%1,%2,%3};"
        : "+f"(d[0]), "+f"(d[1]), "+f"(d[2]), "+f"(d[3])
        : "r"(a[0]), "r"(a[1]), "r"(a[2]), "r"(a[3]),
          "r"(b[0]), "r"(b[1]));
}
__device__ __forceinline__ float gelu_exact(float v)
{
    return 0.5f * v * (1.f + erff(v * 0.7071067811865476f));
}
__device__ __forceinline__ uint32_t packh2(float a, float b) {
    __half2 h = __floats2half2_rn(a, b);
    return *reinterpret_cast<uint32_t*>(&h);
}

// ---------------------------------------------------------------------------
// LayerNorm (LN1): one warp per row, 8 rows per 256-thread block.
// ---------------------------------------------------------------------------
__global__ void ln_kernel(const float* __restrict__ x,
                          const float* __restrict__ g,
                          const float* __restrict__ b,
                          __half* __restrict__ y)
{
    int  lane = threadIdx.x & 31;
    long row  = (long)blockIdx.x * 8 + (threadIdx.x >> 5);
    const float* xr = x + row * DIMC;

    float4 v0 = *reinterpret_cast<const float4*>(xr + lane * 4);
    float4 v1 = *reinterpret_cast<const float4*>(xr + 128 + lane * 4);

    float s  = v0.x + v0.y + v0.z + v0.w + v1.x + v1.y + v1.z + v1.w;
    float s2 = v0.x * v0.x + v0.y * v0.y + v0.z * v0.z + v0.w * v0.w +
               v1.x * v1.x + v1.y * v1.y + v1.z * v1.z + v1.w * v1.w;
    #pragma unroll
    for (int o = 16; o; o >>= 1) {
        s  += __shfl_xor_sync(0xffffffffu, s,  o);
        s2 += __shfl_xor_sync(0xffffffffu, s2, o);
    }
    float mu  = s  * (1.f / DIMC);
    float var = s2 * (1.f / DIMC) - mu * mu;
    float inv = rsqrtf(var + 1e-5f);

    float4 g0 = *reinterpret_cast<const float4*>(g + lane * 4);
    float4 b0 = *reinterpret_cast<const float4*>(b + lane * 4);
    float4 g1 = *reinterpret_cast<const float4*>(g + 128 + lane * 4);
    float4 b1 = *reinterpret_cast<const float4*>(b + 128 + lane * 4);

    uint2 o0, o1;
    o0.x = packh2((v0.x - mu) * inv * g0.x + b0.x,
                  (v0.y - mu) * inv * g0.y + b0.y);
    o0.y = packh2((v0.z - mu) * inv * g0.z + b0.z,
                  (v0.w - mu) * inv * g0.w + b0.w);
    o1.x = packh2((v1.x - mu) * inv * g1.x + b1.x,
                  (v1.y - mu) * inv * g1.y + b1.y);
    o1.y = packh2((v1.z - mu) * inv * g1.z + b1.z,
                  (v1.w - mu) * inv * g1.w + b1.w);
    *reinterpret_cast<uint2*>(y + row * DIMC + lane * 4)       = o0;
    *reinterpret_cast<uint2*>(y + row * DIMC + 128 + lane * 4) = o1;
}

// ---------------------------------------------------------------------------
// Merged weight transpose (single launch). fp32 [R,C] -> half [C,R]
// ---------------------------------------------------------------------------
__global__ void transpose_all_kernel(const float* __restrict__ wqkv,
                                     const float* __restrict__ wout,
                                     const float* __restrict__ w1,
                                     const float* __restrict__ w2,
                                     __half* __restrict__ owqkv,
                                     __half* __restrict__ owout,
                                     __half* __restrict__ ow1,
                                     __half* __restrict__ ow2)
{
    __shared__ float t[32][33];
    int bid = blockIdx.x;
    const float* in; __half* out; int R, C, tx_, ty_;
    if (bid < 192)      { in = wqkv; out = owqkv; R = DIMC; C = 768;
                          tx_ = bid % 24; ty_ = bid / 24; }
    else if (bid < 256) { bid -= 192; in = wout; out = owout; R = DIMC; C = DIMC;
                          tx_ = bid % 8;  ty_ = bid / 8; }
    else if (bid < 512) { bid -= 256; in = w1;   out = ow1;   R = DIMC; C = MLPD;
                          tx_ = bid % 32; ty_ = bid / 32; }
    else                { bid -= 512; in = w2;   out = ow2;   R = MLPD; C = DIMC;
                          tx_ = bid % 8;  ty_ = bid / 8; }
    int bx = tx_ * 32, by = ty_ * 32;
    #pragma unroll
    for (int i = threadIdx.y; i < 32; i += 8)
        t[i][threadIdx.x] = in[(long)(by + i) * C + bx + threadIdx.x];
    __syncthreads();
    #pragma unroll
    for (int i = threadIdx.y; i < 32; i += 8)
        out[(long)(bx + i) * R + by + threadIdx.x] =
            __float2half(t[threadIdx.x][i]);
}

// ---------------------------------------------------------------------------
// fp16 GEMM (r11 config): 128x128 CTA tile, BK=64h, 4 warps (2x2, 64x64),
// 3-stage cp.async, 96KB smem, 2 CTAs/SM.
// ---------------------------------------------------------------------------
#define EPI_NONE      0
#define EPI_GELU_BIAS 2
#define EPI_BIAS_ACC  3

#define BM  128
#define BN  128
#define BKH 64
#define A_BYTES   16384
#define STG_BYTES 32768
#define STAGES    3
#define GEMM_SMEM_BYTES (STAGES * STG_BYTES)
#define GTHR 128

template <int EPI>
__global__ __launch_bounds__(GTHR, 2)
void hgemm(const __half* __restrict__ A, const __half* __restrict__ Bt,
           void* __restrict__ Cv,
           const float* __restrict__ bias,
           int M, int N, int K)
{
    extern __shared__ char smem[];
    uint32_t sbase = smem_u32(smem);

    int  tid    = threadIdx.x;
    int  lane   = tid & 31;
    int  wid    = tid >> 5;
    int  warp_m = wid >> 1;
    int  warp_n = wid & 1;
    long m0     = (long)blockIdx.y * BM;
    int  n0     = blockIdx.x * BN;
    int  nc     = K / BKH;

    int l_row = tid >> 3;
    int l_grp = tid & 7;
    uint32_t l_off = (uint32_t)(l_row * 128 + ((l_grp ^ (l_row & 7)) << 4));

    auto ldgsts = [&](int kc, int st) {
        uint32_t sb = sbase + (uint32_t)st * STG_BYTES + l_off;
        const __half* Ap = A  + (m0 + l_row) * K + kc * BKH + l_grp * 8;
        #pragma unroll
        for (int it = 0; it < 8; it++)
            cpa16(sb + (uint32_t)(it * 16 * 128), Ap + (long)(it * 16) * K);
        const __half* Bp = Bt + ((long)n0 + l_row) * K + kc * BKH + l_grp * 8;
        #pragma unroll
        for (int it = 0; it < 8; it++)
            cpa16(sb + (uint32_t)(A_BYTES + it * 16 * 128),
                  Bp + (long)(it * 16) * K);
        CPA_COMMIT();
    };

    float acc[4][8][4];
    #pragma unroll
    for (int i = 0; i < 4; i++)
        #pragma unroll
        for (int j = 0; j < 8; j++)
            #pragma unroll
            for (int e = 0; e < 4; e++) acc[i][j][e] = 0.f;

    ldgsts(0, 0);
    if (nc > 1) ldgsts(1, 1);

    int a_row_l = (lane & 15);
    int a_kg_l  = (lane >> 4);
    int b_row_l = ((lane >> 4) << 3) + (lane & 7);
    int b_kg_l  = (lane >> 3) & 1;

    for (int c = 0; c < nc; c++) {
        if (c + 2 < nc) ldgsts(c + 2, (c + 2) % STAGES);

        int rem = nc - 1 - c; if (rem > 2) rem = 2;
        if (rem == 2)      asm volatile("cp.async.wait_group 2;" ::: "memory");
        else if (rem == 1) asm volatile("cp.async.wait_group 1;" ::: "memory");
        else               asm volatile("cp.async.wait_group 0;" ::: "memory");
        __syncthreads();

        uint32_t smA = sbase + (uint32_t)(c % STAGES) * STG_BYTES;
        uint32_t smB = smA + A_BYTES;

        #pragma unroll
        for (int ks = 0; ks < 4; ks++) {
            uint32_t af[4][4];
            #pragma unroll
            for (int mf = 0; mf < 4; mf++) {
                int row  = warp_m * 64 + mf * 16 + a_row_l;
                int grpk = ks * 2 + a_kg_l;
                uint32_t addr = smA + row * 128 +
                                (((grpk ^ (row & 7)) & 7) << 4);
                ldsm4(af[mf][0], af[mf][1], af[mf][2], af[mf][3], addr);
            }
            uint32_t bf[8][2];
            #pragma unroll
            for (int np = 0; np < 4; np++) {
                int row  = warp_n * 64 + np * 16 + b_row_l;
                int grpk = ks * 2 + b_kg_l;
                uint32_t addr = smB + row * 128 +
                                (((grpk ^ (row & 7)) & 7) << 4);
                uint32_t r0, r1, r2, r3;
                ldsm4(r0, r1, r2, r3, addr);
                bf[np * 2][0]     = r0; bf[np * 2][1]     = r1;
                bf[np * 2 + 1][0] = r2; bf[np * 2 + 1][1] = r3;
            }
            #pragma unroll
            for (int mf = 0; mf < 4; mf++)
                #pragma unroll
                for (int nf = 0; nf < 8; nf++)
                    mma_f16(acc[mf][nf], af[mf], bf[nf]);
        }
        __syncthreads();
    }

    int g = lane >> 2;
    int q = lane & 3;

    float2 bv[8];
    if (EPI != EPI_NONE) {
        #pragma unroll
        for (int nf = 0; nf < 8; nf++) {
            int col = n0 + warp_n * 64 + nf * 8 + q * 2;
            bv[nf] = *reinterpret_cast<const float2*>(&bias[col]);
        }
    }

    #pragma unroll
    for (int mf = 0; mf < 4; mf++) {
        long r0 = m0 + warp_m * 64 + mf * 16 + g;
        long r1 = r0 + 8;
        #pragma unroll
        for (int nf = 0; nf < 8; nf++) {
            int col = n0 + warp_n * 64 + nf * 8 + q * 2;
            float2 v0 = make_float2(acc[mf][nf][0], acc[mf][nf][1]);
            float2 v1 = make_float2(acc[mf][nf][2], acc[mf][nf][3]);
            if (EPI == EPI_NONE) {
                __half* C = (__half*)Cv;
                *reinterpret_cast<__half2*>(&C[r0 * N + col]) =
                    __floats2half2_rn(v0.x, v0.y);
                *reinterpret_cast<__half2*>(&C[r1 * N + col]) =
                    __floats2half2_rn(v1.x, v1.y);
            } else if (EPI == EPI_GELU_BIAS) {
                __half* C = (__half*)Cv;
                *reinterpret_cast<__half2*>(&C[r0 * N + col]) =
                    __floats2half2_rn(gelu_exact(v0.x + bv[nf].x),
                                      gelu_exact(v0.y + bv[nf].y));
                *reinterpret_cast<__half2*>(&C[r1 * N + col]) =
                    __floats2half2_rn(gelu_exact(v1.x + bv[nf].x),
                                      gelu_exact(v1.y + bv[nf].y));
            } else { // EPI_BIAS_ACC
                float* C = (float*)Cv;
                float2 e0 = *reinterpret_cast<const float2*>(&C[r0 * N + col]);
                float2 e1 = *reinterpret_cast<const float2*>(&C[r1 * N + col]);
                v0.x += bv[nf].x + e0.x; v0.y += bv[nf].y + e0.y;
                v1.x += bv[nf].x + e1.x; v1.y += bv[nf].y + e1.y;
                *reinterpret_cast<float2*>(&C[r0 * N + col]) = v0;
                *reinterpret_cast<float2*>(&C[r1 * N + col]) = v1;
            }
        }
    }
}

// ---------------------------------------------------------------------------
// proj GEMM with fused residual + LN2: BN=256 (full row per CTA), 256 thr,
// 8 warps (2m x 4n, warp tile 64x64), 3-stage cp.async (144KB), 1 CTA/SM.
// Epilogue: stage fp32 (acc+bias+res) in padded smem, warp-per-row LN ->
// writes out (fp32) AND ln (half).
// ---------------------------------------------------------------------------
#define PJ_BN  256
#define PJ_A_BYTES 16384
#define PJ_STG (PJ_A_BYTES + 32768)           // 49152
#define PJ_SMEM (STAGES * PJ_STG)             // 147456
#define FT_STRIDE 260                          // padded fp32 row stride

__global__ __launch_bounds__(256, 1)
void hgemm_proj_ln(const __half* __restrict__ A, const __half* __restrict__ Bt,
                   float* __restrict__ Out, __half* __restrict__ Ln,
                   const float* __restrict__ bias,
                   const float* __restrict__ res,
                   const float* __restrict__ ln_g,
                   const float* __restrict__ ln_b,
                   int M, int K)
{
    extern __shared__ char smem[];
    uint32_t sbase = smem_u32(smem);
    const int N = DIMC;   // 256

    int  tid    = threadIdx.x;
    int  lane   = tid & 31;
    int  wid    = tid >> 5;
    int  warp_m = wid >> 2;          // 0..1
    int  warp_n = wid & 3;           // 0..3
    long m0     = (long)blockIdx.y * BM;
    int  nc     = K / BKH;

    int l_row = tid >> 3;            // 0..31
    int l_grp = tid & 7;
    uint32_t l_off = (uint32_t)(l_row * 128 + ((l_grp ^ (l_row & 7)) << 4));

    auto ldgsts = [&](int kc, int st) {
        uint32_t sb = sbase + (uint32_t)st * PJ_STG + l_off;
        const __half* Ap = A + (m0 + l_row) * K + kc * BKH + l_grp * 8;
        #pragma unroll
        for (int it = 0; it < 4; it++)
            cpa16(sb + (uint32_t)(it * 32 * 128), Ap + (long)(it * 32) * K);
        const __half* Bp = Bt + (long)l_row * K + kc * BKH + l_grp * 8;
        #pragma unroll
        for (int it = 0; it < 8; it++)
            cpa16(sb + (uint32_t)(PJ_A_BYTES + it * 32 * 128),
                  Bp + (long)(it * 32) * K);
        CPA_COMMIT();
    };

    float acc[4][8][4];
    #pragma unroll
    for (int i = 0; i < 4; i++)
        #pragma unroll
        for (int j = 0; j < 8; j++)
            #pragma unroll
            for (int e = 0; e < 4; e++) acc[i][j][e] = 0.f;

    ldgsts(0, 0);
    if (nc > 1) ldgsts(1, 1);

    int a_row_l = (lane & 15);
    int a_kg_l  = (lane >> 4);
    int b_row_l = ((lane >> 4) << 3) + (lane & 7);
    int b_kg_l  = (lane >> 3) & 1;

    for (int c = 0; c < nc; c++) {
        if (c + 2 < nc) ldgsts(c + 2, (c + 2) % STAGES);

        int rem = nc - 1 - c; if (rem > 2) rem = 2;
        if (rem == 2)      asm volatile("cp.async.wait_group 2;" ::: "memory");
        else if (rem == 1) asm volatile("cp.async.wait_group 1;" ::: "memory");
        else               asm volatile("cp.async.wait_group 0;" ::: "memory");
        __syncthreads();

        uint32_t smA = sbase + (uint32_t)(c % STAGES) * PJ_STG;
        uint32_t smB = smA + PJ_A_BYTES;

        #pragma unroll
        for (int ks = 0; ks < 4; ks++) {
            uint32_t af[4][4];
            #pragma unroll
            for (int mf = 0; mf < 4; mf++) {
                int row  = warp_m * 64 + mf * 16 + a_row_l;
                int grpk = ks * 2 + a_kg_l;
                uint32_t addr = smA + row * 128 +
                                (((grpk ^ (row & 7)) & 7) << 4);
                ldsm4(af[mf][0], af[mf][1], af[mf][2], af[mf][3], addr);
            }
            uint32_t bf[8][2];
            #pragma unroll
            for (int np = 0; np < 4; np++) {
                int row  = warp_n * 64 + np * 16 + b_row_l;
                int grpk = ks * 2 + b_kg_l;
                uint32_t addr = smB + row * 128 +
                                (((grpk ^ (row & 7)) & 7) << 4);
                uint32_t r0, r1, r2, r3;
                ldsm4(r0, r1, r2, r3, addr);
                bf[np * 2][0]     = r0; bf[np * 2][1]     = r1;
                bf[np * 2 + 1][0] = r2; bf[np * 2 + 1][1] = r3;
            }
            #pragma unroll
            for (int mf = 0; mf < 4; mf++)
                #pragma unroll
                for (int nf = 0; nf < 8; nf++)
                    mma_f16(acc[mf][nf], af[mf], bf[nf]);
        }
        __syncthreads();
    }

    // ---- epilogue: stage acc+bias+res into padded fp32 smem tile ----
    float* ft = reinterpret_cast<float*>(smem);
    int g = lane >> 2;
    int q = lane & 3;

    float2 bv[8];
    #pragma unroll
    for (int nf = 0; nf < 8; nf++) {
        int col = warp_n * 64 + nf * 8 + q * 2;
        bv[nf] = *reinterpret_cast<const float2*>(&bias[col]);
    }

    #pragma unroll
    for (int mf = 0; mf < 4; mf++) {
        int  lr0 = warp_m * 64 + mf * 16 + g;
        int  lr1 = lr0 + 8;
        long gr0 = m0 + lr0, gr1 = m0 + lr1;
        #pragma unroll
        for (int nf = 0; nf < 8; nf++) {
            int col = warp_n * 64 + nf * 8 + q * 2;
            float2 e0 = *reinterpret_cast<const float2*>(&res[gr0 * N + col]);
            float2 e1 = *reinterpret_cast<const float2*>(&res[gr1 * N + col]);
            float2 v0 = make_float2(acc[mf][nf][0] + bv[nf].x + e0.x,
                                    acc[mf][nf][1] + bv[nf].y + e0.y);
            float2 v1 = make_float2(acc[mf][nf][2] + bv[nf].x + e1.x,
                                    acc[mf][nf][3] + bv[nf].y + e1.y);
            *reinterpret_cast<float2*>(&ft[lr0 * FT_STRIDE + col]) = v0;
            *reinterpret_cast<float2*>(&ft[lr1 * FT_STRIDE + col]) = v1;
        }
    }
    __syncthreads();

    // ---- warp-per-row LN over the smem tile; write out fp32 + ln half ----
    #pragma unroll
    for (int i = 0; i < 16; i++) {
        int  lr  = wid * 16 + i;
        long grow = m0 + lr;
        const float* fr = &ft[lr * FT_STRIDE];
        float4 v0 = *reinterpret_cast<const float4*>(fr + lane * 8);
        float4 v1 = *reinterpret_cast<const float4*>(fr + lane * 8 + 4);

        float s  = v0.x + v0.y + v0.z + v0.w + v1.x + v1.y + v1.z + v1.w;
        float s2 = v0.x * v0.x + v0.y * v0.y + v0.z * v0.z + v0.w * v0.w +
                   v1.x * v1.x + v1.y * v1.y + v1.z * v1.z + v1.w * v1.w;
        #pragma unroll
        for (int o = 16; o; o >>= 1) {
            s  += __shfl_xor_sync(0xffffffffu, s,  o);
            s2 += __shfl_xor_sync(0xffffffffu, s2, o);
        }
        float mu  = s  * (1.f / DIMC);
        float var = s2 * (1.f / DIMC) - mu * mu;
        float inv = rsqrtf(var + 1e-5f);

        *reinterpret_cast<float4*>(Out + grow * N + lane * 8)     = v0;
        *reinterpret_cast<float4*>(Out + grow * N + lane * 8 + 4) = v1;

        float4 lg0 = *reinterpret_cast<const float4*>(ln_g + lane * 8);
        float4 lg1 = *reinterpret_cast<const float4*>(ln_g + lane * 8 + 4);
        float4 lb0 = *reinterpret_cast<const float4*>(ln_b + lane * 8);
        float4 lb1 = *reinterpret_cast<const float4*>(ln_b + lane * 8 + 4);

        uint4 ho;
        ho.x = packh2((v0.x - mu) * inv * lg0.x + lb0.x,
                      (v0.y - mu) * inv * lg0.y + lb0.y);
        ho.y = packh2((v0.z - mu) * inv * lg0.z + lb0.z,
                      (v0.w - mu) * inv * lg0.w + lb0.w);
        ho.z = packh2((v1.x - mu) * inv * lg1.x + lb1.x,
                      (v1.y - mu) * inv * lg1.y + lb1.y);
        ho.w = packh2((v1.z - mu) * inv * lg1.z + lb1.z,
                      (v1.w - mu) * inv * lg1.w + lb1.w);
        *reinterpret_cast<uint4*>(Ln + grow * N + lane * 8) = ho;
    }
}

// ---------------------------------------------------------------------------
// Tensor-core window attention (r12): 4 heads per 128-thread CTA, 2 CTAs/SM.
// ---------------------------------------------------------------------------
#define AROW_B    768
#define AQKV_B    (WS * AROW_B)
#define POS_PAD   68
#define ATTN_SMEM (AQKV_B + WS * POS_PAD * 4)

__global__ __launch_bounds__(128, 2)
void attn_mma_kernel(const __half* __restrict__ qkv,
                     const float* __restrict__ pos,
                     __half* __restrict__ out)
{
    extern __shared__ char smem[];
    uint32_t sb = smem_u32(smem);
    float* pos_s = reinterpret_cast<float*>(smem + AQKV_B);

    int tid  = threadIdx.x;
    int lane = tid & 31;
    int w    = tid >> 5;
    int win  = blockIdx.x;
    int yh   = blockIdx.y;
    int b    = blockIdx.z;

    #pragma unroll
    for (int it = 0; it < 24; it++) {
        int slot = it * 128 + tid;
        int row  = slot / 48;
        int grp  = slot % 48;
        int sec  = grp >> 4;
        int within = grp & 15;
        int srcgrp = sec * 32 + yh * 16 + within;
        long t = (long)b * NPB + ((win * WS + WS / 2 + row) & (NPB - 1));
        cpa16(sb + row * AROW_B + ((grp ^ (row & 7)) << 4),
              qkv + t * 768 + srcgrp * 8);
    }
    #pragma unroll
    for (int it = 0; it < 8; it++) {
        int slot = it * 128 + tid;
        int row  = slot >> 4;
        int c4   = slot & 15;
        cpa16(sb + AQKV_B + (uint32_t)(row * POS_PAD + c4 * 4) * 4,
              pos + row * 64 + c4 * 4);
    }
    CPA_COMMIT();
    asm volatile("cp.async.wait_group 0;" ::: "memory");
    __syncthreads();

    int g = lane >> 2;
    int q = lane & 3;

    float dots[4][8][4];
    #pragma unroll
    for (int i = 0; i < 4; i++)
        #pragma unroll
        for (int j = 0; j < 8; j++)
            #pragma unroll
            for (int e = 0; e < 4; e++) dots[i][j][e] = 0.f;

    int a_row_l = lane & 15;
    int a_kg_l  = lane >> 4;
    int b_row_l = ((lane >> 4) << 3) + (lane & 7);
    int b_kg_l  = (lane >> 3) & 1;

    #pragma unroll
    for (int ks = 0; ks < 2; ks++) {
        uint32_t af[4][4];
        #pragma unroll
        for (int mf = 0; mf < 4; mf++) {
            int row = mf * 16 + a_row_l;
            int grp = w * 4 + ks * 2 + a_kg_l;
            uint32_t addr = sb + row * AROW_B + ((grp ^ (row & 7)) << 4);
            ldsm4(af[mf][0], af[mf][1], af[mf][2], af[mf][3], addr);
        }
        uint32_t bf[8][2];
        #pragma unroll
        for (int np = 0; np < 4; np++) {
            int row = np * 16 + b_row_l;
            int grp = 16 + w * 4 + ks * 2 + b_kg_l;
            uint32_t addr = sb + row * AROW_B + ((grp ^ (row & 7)) << 4);
            uint32_t r0, r1, r2, r3;
            ldsm4(r0, r1, r2, r3, addr);
            bf[np * 2][0]     = r0; bf[np * 2][1]     = r1;
            bf[np * 2 + 1][0] = r2; bf[np * 2 + 1][1] = r3;
        }
        #pragma unroll
        for (int mf = 0; mf < 4; mf++)
            #pragma unroll
            for (int nf = 0; nf < 8; nf++)
                mma_f16(dots[mf][nf], af[mf], bf[nf]);
    }

    const float scale = 0.17677669529663687f;
    float inv_l[4][2];
    #pragma unroll
    for (int mf = 0; mf < 4; mf++) {
        #pragma unroll
        for (int rp = 0; rp < 2; rp++) {
            int row = mf * 16 + g + rp * 8;
            float m = -1e30f;
            #pragma unroll
            for (int nf = 0; nf < 8; nf++) {
                float2 pp = *reinterpret_cast<const float2*>(
                    &pos_s[row * POS_PAD + nf * 8 + 2 * q]);
                float c0 = dots[mf][nf][rp * 2 + 0] * scale + pp.x;
                float c1 = dots[mf][nf][rp * 2 + 1] * scale + pp.y;
                dots[mf][nf][rp * 2 + 0] = c0;
                dots[mf][nf][rp * 2 + 1] = c1;
                m = fmaxf(m, fmaxf(c0, c1));
            }
            m = fmaxf(m, __shfl_xor_sync(0xffffffffu, m, 1));
            m = fmaxf(m, __shfl_xor_sync(0xffffffffu, m, 2));
            float s = 0.f;
            #pragma unroll
            for (int nf = 0; nf < 8; nf++) {
                float e0 = __expf(dots[mf][nf][rp * 2 + 0] - m);
                float e1 = __expf(dots[mf][nf][rp * 2 + 1] - m);
                dots[mf][nf][rp * 2 + 0] = e0;
                dots[mf][nf][rp * 2 + 1] = e1;
                s += e0 + e1;
            }
            s += __shfl_xor_sync(0xffffffffu, s, 1);
            s += __shfl_xor_sync(0xffffffffu, s, 2);
            inv_l[mf][rp] = 1.f / s;
        }
    }

    uint32_t p[4][4][4];
    #pragma unroll
    for (int mf = 0; mf < 4; mf++)
        #pragma unroll
        for (int ks = 0; ks < 4; ks++) {
            p[mf][ks][0] = packh2(dots[mf][2 * ks][0],     dots[mf][2 * ks][1]);
            p[mf][ks][1] = packh2(dots[mf][2 * ks][2],     dots[mf][2 * ks][3]);
            p[mf][ks][2] = packh2(dots[mf][2 * ks + 1][0], dots[mf][2 * ks + 1][1]);
            p[mf][ks][3] = packh2(dots[mf][2 * ks + 1][2], dots[mf][2 * ks + 1][3]);
        }

    float o[4][4][4];
    #pragma unroll
    for (int i = 0; i < 4; i++)
        #pragma unroll
        for (int j = 0; j < 4; j++)
            #pragma unroll
            for (int e = 0; e < 4; e++) o[i][j][e] = 0.f;

    #pragma unroll
    for (int ks = 0; ks < 4; ks++) {
        uint32_t bb[4][2];
        #pragma unroll
        for (int hf = 0; hf < 2; hf++) {
            int row = ks * 16 + (lane & 15);
            int grp = 32 + w * 4 + 2 * hf + (lane >> 4);
            uint32_t addr = sb + row * AROW_B + ((grp ^ (row & 7)) << 4);
            uint32_t r0, r1, r2, r3;
            ldsm4t(r0, r1, r2, r3, addr);
            bb[2 * hf][0]     = r0; bb[2 * hf][1]     = r1;
            bb[2 * hf + 1][0] = r2; bb[2 * hf + 1][1] = r3;
        }
        #pragma unroll
        for (int mf = 0; mf < 4; mf++)
            #pragma unroll
            for (int nf = 0; nf < 4; nf++)
                mma_f16(o[mf][nf], p[mf][ks], bb[nf]);
    }

    #pragma unroll
    for (int mf = 0; mf < 4; mf++) {
        #pragma unroll
        for (int rp = 0; rp < 2; rp++) {
            int r = mf * 16 + g + rp * 8;
            float il = inv_l[mf][rp];
            #pragma unroll
            for (int nf = 0; nf < 4; nf++) {
                uint32_t addr = sb + r * AROW_B +
                                (((w * 4 + nf) ^ (r & 7)) << 4) + 4 * q;
                uint32_t vv = packh2(o[mf][nf][rp * 2 + 0] * il,
                                     o[mf][nf][rp * 2 + 1] * il);
                asm volatile("st.shared.b32 [%0], %1;" :: "r"(addr), "r"(vv)
                             : "memory");
            }
        }
    }
    __syncthreads();

    #pragma unroll
    for (int it = 0; it < 8; it++) {
        int slot = it * 128 + tid;
        int row  = slot >> 4;
        int gi   = slot & 15;
        uint32_t addr = sb + row * AROW_B + ((gi ^ (row & 7)) << 4);
        uint4 vv;
        asm volatile("ld.shared.v4.b32 {%0,%1,%2,%3}, [%4];"
                     : "=r"(vv.x), "=r"(vv.y), "=r"(vv.z), "=r"(vv.w)
                     : "r"(addr));
        long t = (long)b * NPB + ((win * WS + WS / 2 + row) & (NPB - 1));
        *reinterpret_cast<uint4*>(&out[t * DIMC + yh * 128 + gi * 8]) = vv;
    }
}

// ---------------------------------------------------------------------------
// launch
// ---------------------------------------------------------------------------
extern "C" void kernel_launch(void* const* d_in, const int* in_sizes, int n_in,
                              void* d_out, int out_size)
{
    const float* x      = (const float*)d_in[0];
    const float* w_qkv  = (const float*)d_in[1];
    const float* w_out  = (const float*)d_in[2];
    const float* b_out  = (const float*)d_in[3];
    const float* pos    = (const float*)d_in[4];
    const float* ln1_g  = (const float*)d_in[5];
    const float* ln1_b  = (const float*)d_in[6];
    const float* w1     = (const float*)d_in[7];
    const float* b1     = (const float*)d_in[8];
    const float* w2     = (const float*)d_in[9];
    const float* b2     = (const float*)d_in[10];
    const float* ln2_g  = (const float*)d_in[11];
    const float* ln2_b  = (const float*)d_in[12];
    float* out = (float*)d_out;

    int tokens = in_sizes[0] / DIMC;   // 131072

    __half *p_ln, *p_qkv, *p_attn, *p_h, *p_wqkvT, *p_woutT, *p_w1T, *p_w2T;
    cudaGetSymbolAddress((void**)&p_ln,    g_ln);
    cudaGetSymbolAddress((void**)&p_qkv,   g_qkv);
    cudaGetSymbolAddress((void**)&p_attn,  g_attn);
    cudaGetSymbolAddress((void**)&p_h,     g_h);
    cudaGetSymbolAddress((void**)&p_wqkvT, g_wqkvT);
    cudaGetSymbolAddress((void**)&p_woutT, g_woutT);
    cudaGetSymbolAddress((void**)&p_w1T,   g_w1T);
    cudaGetSymbolAddress((void**)&p_w2T,   g_w2T);

    cudaFuncSetAttribute(hgemm<EPI_NONE>,
        cudaFuncAttributeMaxDynamicSharedMemorySize, GEMM_SMEM_BYTES);
    cudaFuncSetAttribute(hgemm<EPI_GELU_BIAS>,
        cudaFuncAttributeMaxDynamicSharedMemorySize, GEMM_SMEM_BYTES);
    cudaFuncSetAttribute(hgemm<EPI_BIAS_ACC>,
        cudaFuncAttributeMaxDynamicSharedMemorySize, GEMM_SMEM_BYTES);
    cudaFuncSetAttribute(hgemm_proj_ln,
        cudaFuncAttributeMaxDynamicSharedMemorySize, PJ_SMEM);
    cudaFuncSetAttribute(attn_mma_kernel,
        cudaFuncAttributeMaxDynamicSharedMemorySize, ATTN_SMEM);

    // #1: merged transposes (single launch)
    transpose_all_kernel<<<768, dim3(32, 8)>>>(
        w_qkv, w_out, w1, w2, p_wqkvT, p_woutT, p_w1T, p_w2T);

    // #2: LN1 (warp-per-row)
    ln_kernel<<<tokens / 8, 256>>>(x, ln1_g, ln1_b, p_ln);

    // #3: QKV GEMM
    {
        dim3 grid(768 / BN, tokens / BM);
        hgemm<EPI_NONE><<<grid, GTHR, GEMM_SMEM_BYTES>>>(
            p_ln, p_wqkvT, p_qkv, nullptr, tokens, 768, DIMC);
    }

    // #4: attention (ncu capture slot = global launch #6)
    {
        dim3 grid(NPB / WS, 2, tokens / NPB);
        attn_mma_kernel<<<grid, 128, ATTN_SMEM>>>(p_qkv, pos, p_attn);
    }

    // #5: proj + residual + LN2 fused -> out (fp32) and g_ln (half)
    {
        dim3 grid(1, tokens / BM);
        hgemm_proj_ln<<<grid, 256, PJ_SMEM>>>(
            p_attn, p_woutT, out, p_ln, b_out, x, ln2_g, ln2_b,
            tokens, DIMC);
    }

    // #6: MLP1 + GELU
    {
        dim3 grid(MLPD / BN, tokens / BM);
        hgemm<EPI_GELU_BIAS><<<grid, GTHR, GEMM_SMEM_BYTES>>>(
            p_ln, p_w1T, p_h, b1, tokens, MLPD, DIMC);
    }

    // #7: MLP2 accumulate
    {
        dim3 grid(DIMC / BN, tokens / BM);
        hgemm<EPI_BIAS_ACC><<<grid, GTHR, GEMM_SMEM_BYTES>>>(
            p_h, p_w2T, out, b2, tokens, DIMC, MLPD);
    }
}

// round 15
// speedup vs baseline: 1.0196x; 1.0196x over previous
#include <cuda_runtime.h>
#include <cuda_fp16.h>
#include <math.h>
#include <stdint.h>

// ---------------------------------------------------------------------------
// PointSwinBlock on GB300 (sm_103): fp16 mma.sync GEMMs (at legacy-HMMA
// ceiling) + 2-CTA/SM TC window attention + warp-row LN.
// Round 14 = round 12 (best measured) + single merged transpose launch.
// B=2, N=65536, DIM=256, HEADS=8, HEAD_DIM=32, WS=64, MLP=1024
// ---------------------------------------------------------------------------

#define DIMC   256
#define NTOK   131072
#define NPB    65536
#define HEADS  8
#define HDIM   32
#define WS     64
#define MLPD   1024

__device__ __half g_ln  [(size_t)NTOK * DIMC];
__device__ __half g_qkv [(size_t)NTOK * 768];
__device__ __half g_attn[(size_t)NTOK * DIMC];
__device__ __half g_h   [(size_t)NTOK * MLPD];
__device__ __half g_wqkvT[768 * DIMC];
__device__ __half g_woutT[DIMC * DIMC];
__device__ __half g_w1T  [MLPD * DIMC];
__device__ __half g_w2T  [DIMC * MLPD];

__device__ __forceinline__ uint32_t smem_u32(const void* p) {
    uint32_t a;
    asm("{ .reg .u64 t; cvta.to.shared.u64 t, %1; cvt.u32.u64 %0, t; }"
        : "=r"(a) : "l"(p));
    return a;
}
__device__ __forceinline__ void cpa16(uint32_t dst, const void* src) {
    asm volatile("cp.async.cg.shared.global [%0], [%1], 16;"
                 :: "r"(dst), "l"(src) : "memory");
}
#define CPA_COMMIT() asm volatile("cp.async.commit_group;" ::: "memory")

__device__ __forceinline__ void ldsm4(uint32_t& r0, uint32_t& r1,
                                      uint32_t& r2, uint32_t& r3,
                                      uint32_t addr) {
    asm volatile("ldmatrix.sync.aligned.m8n8.x4.shared.b16 {%0,%1,%2,%3}, [%4];"
                 : "=r"(r0), "=r"(r1), "=r"(r2), "=r"(r3) : "r"(addr));
}
__device__ __forceinline__ void ldsm4t(uint32_t& r0, uint32_t& r1,
                                       uint32_t& r2, uint32_t& r3,
                                       uint32_t addr) {
    asm volatile("ldmatrix.sync.aligned.m8n8.x4.trans.shared.b16 {%0,%1,%2,%3}, [%4];"
                 : "=r"(r0), "=r"(r1), "=r"(r2), "=r"(r3) : "r"(addr));
}
__device__ __forceinline__ void mma_f16(float* d, const uint32_t* a,
                                        const uint32_t* b) {
    asm volatile(
        "mma.sync.aligned.m16n8k16.row.col.f32.f16.f16.f32 "
        "{%0,%1,%2,%3}, {%4,%5,%6,%7}, {%8,%9}, {%0,%1,%2,%3};"
        : "+f"(d[0]), "+f"(d[1]), "+f"(d[2]), "+f"(d[3])
        : "r"(a[0]), "r"(a[1]), "r"(a[2]), "r"(a[3]),
          "r"(b[0]), "r"(b[1]));
}
__device__ __forceinline__ float gelu_exact(float v)
{
    return 0.5f * v * (1.f + erff(v * 0.7071067811865476f));
}
__device__ __forceinline__ uint32_t packh2(float a, float b) {
    __half2 h = __floats2half2_rn(a, b);
    return *reinterpret_cast<uint32_t*>(&h);
}

// ---------------------------------------------------------------------------
// LayerNorm: one warp per row, 8 rows per 256-thread block.
// ---------------------------------------------------------------------------
__global__ void ln_kernel(const float* __restrict__ x,
                          const float* __restrict__ g,
                          const float* __restrict__ b,
                          __half* __restrict__ y)
{
    int  lane = threadIdx.x & 31;
    long row  = (long)blockIdx.x * 8 + (threadIdx.x >> 5);
    const float* xr = x + row * DIMC;

    float4 v0 = *reinterpret_cast<const float4*>(xr + lane * 4);
    float4 v1 = *reinterpret_cast<const float4*>(xr + 128 + lane * 4);

    float s  = v0.x + v0.y + v0.z + v0.w + v1.x + v1.y + v1.z + v1.w;
    float s2 = v0.x * v0.x + v0.y * v0.y + v0.z * v0.z + v0.w * v0.w +
               v1.x * v1.x + v1.y * v1.y + v1.z * v1.z + v1.w * v1.w;
    #pragma unroll
    for (int o = 16; o; o >>= 1) {
        s  += __shfl_xor_sync(0xffffffffu, s,  o);
        s2 += __shfl_xor_sync(0xffffffffu, s2, o);
    }
    float mu  = s  * (1.f / DIMC);
    float var = s2 * (1.f / DIMC) - mu * mu;
    float inv = rsqrtf(var + 1e-5f);

    float4 g0 = *reinterpret_cast<const float4*>(g + lane * 4);
    float4 b0 = *reinterpret_cast<const float4*>(b + lane * 4);
    float4 g1 = *reinterpret_cast<const float4*>(g + 128 + lane * 4);
    float4 b1 = *reinterpret_cast<const float4*>(b + 128 + lane * 4);

    uint2 o0, o1;
    o0.x = packh2((v0.x - mu) * inv * g0.x + b0.x,
                  (v0.y - mu) * inv * g0.y + b0.y);
    o0.y = packh2((v0.z - mu) * inv * g0.z + b0.z,
                  (v0.w - mu) * inv * g0.w + b0.w);
    o1.x = packh2((v1.x - mu) * inv * g1.x + b1.x,
                  (v1.y - mu) * inv * g1.y + b1.y);
    o1.y = packh2((v1.z - mu) * inv * g1.z + b1.z,
                  (v1.w - mu) * inv * g1.w + b1.w);
    *reinterpret_cast<uint2*>(y + row * DIMC + lane * 4)       = o0;
    *reinterpret_cast<uint2*>(y + row * DIMC + 128 + lane * 4) = o1;
}

// ---------------------------------------------------------------------------
// Merged weight transpose (single launch). fp32 [R,C] -> half [C,R]
// ---------------------------------------------------------------------------
__global__ void transpose_all_kernel(const float* __restrict__ wqkv,
                                     const float* __restrict__ wout,
                                     const float* __restrict__ w1,
                                     const float* __restrict__ w2,
                                     __half* __restrict__ owqkv,
                                     __half* __restrict__ owout,
                                     __half* __restrict__ ow1,
                                     __half* __restrict__ ow2)
{
    __shared__ float t[32][33];
    int bid = blockIdx.x;
    const float* in; __half* out; int R, C, tx_, ty_;
    if (bid < 192)      { in = wqkv; out = owqkv; R = DIMC; C = 768;
                          tx_ = bid % 24; ty_ = bid / 24; }
    else if (bid < 256) { bid -= 192; in = wout; out = owout; R = DIMC; C = DIMC;
                          tx_ = bid % 8;  ty_ = bid / 8; }
    else if (bid < 512) { bid -= 256; in = w1;   out = ow1;   R = DIMC; C = MLPD;
                          tx_ = bid % 32; ty_ = bid / 32; }
    else                { bid -= 512; in = w2;   out = ow2;   R = MLPD; C = DIMC;
                          tx_ = bid % 8;  ty_ = bid / 8; }
    int bx = tx_ * 32, by = ty_ * 32;
    #pragma unroll
    for (int i = threadIdx.y; i < 32; i += 8)
        t[i][threadIdx.x] = in[(long)(by + i) * C + bx + threadIdx.x];
    __syncthreads();
    #pragma unroll
    for (int i = threadIdx.y; i < 32; i += 8)
        out[(long)(bx + i) * R + by + threadIdx.x] =
            __float2half(t[threadIdx.x][i]);
}

// ---------------------------------------------------------------------------
// fp16 GEMM (r11/r12 config): 128x128 CTA tile, BK=64h, 4 warps (2x2, 64x64),
// 3-stage cp.async, 96KB smem, 2 CTAs/SM.
// ---------------------------------------------------------------------------
#define EPI_NONE      0
#define EPI_BIAS_RES  1
#define EPI_GELU_BIAS 2
#define EPI_BIAS_ACC  3

#define BM  128
#define BN  128
#define BKH 64
#define A_BYTES   16384
#define STG_BYTES 32768
#define STAGES    3
#define GEMM_SMEM_BYTES (STAGES * STG_BYTES)
#define GTHR 128

template <int EPI>
__global__ __launch_bounds__(GTHR, 2)
void hgemm(const __half* __restrict__ A, const __half* __restrict__ Bt,
           void* __restrict__ Cv,
           const float* __restrict__ bias,
           const float* __restrict__ res,
           int M, int N, int K)
{
    extern __shared__ char smem[];
    uint32_t sbase = smem_u32(smem);

    int  tid    = threadIdx.x;
    int  lane   = tid & 31;
    int  wid    = tid >> 5;
    int  warp_m = wid >> 1;
    int  warp_n = wid & 1;
    long m0     = (long)blockIdx.y * BM;
    int  n0     = blockIdx.x * BN;
    int  nc     = K / BKH;

    int l_row = tid >> 3;
    int l_grp = tid & 7;
    uint32_t l_off = (uint32_t)(l_row * 128 + ((l_grp ^ (l_row & 7)) << 4));

    auto ldgsts = [&](int kc, int st) {
        uint32_t sb = sbase + (uint32_t)st * STG_BYTES + l_off;
        const __half* Ap = A  + (m0 + l_row) * K + kc * BKH + l_grp * 8;
        #pragma unroll
        for (int it = 0; it < 8; it++)
            cpa16(sb + (uint32_t)(it * 16 * 128), Ap + (long)(it * 16) * K);
        const __half* Bp = Bt + ((long)n0 + l_row) * K + kc * BKH + l_grp * 8;
        #pragma unroll
        for (int it = 0; it < 8; it++)
            cpa16(sb + (uint32_t)(A_BYTES + it * 16 * 128),
                  Bp + (long)(it * 16) * K);
        CPA_COMMIT();
    };

    float acc[4][8][4];
    #pragma unroll
    for (int i = 0; i < 4; i++)
        #pragma unroll
        for (int j = 0; j < 8; j++)
            #pragma unroll
            for (int e = 0; e < 4; e++) acc[i][j][e] = 0.f;

    ldgsts(0, 0);
    if (nc > 1) ldgsts(1, 1);

    int a_row_l = (lane & 15);
    int a_kg_l  = (lane >> 4);
    int b_row_l = ((lane >> 4) << 3) + (lane & 7);
    int b_kg_l  = (lane >> 3) & 1;

    for (int c = 0; c < nc; c++) {
        if (c + 2 < nc) ldgsts(c + 2, (c + 2) % STAGES);

        int rem = nc - 1 - c; if (rem > 2) rem = 2;
        if (rem == 2)      asm volatile("cp.async.wait_group 2;" ::: "memory");
        else if (rem == 1) asm volatile("cp.async.wait_group 1;" ::: "memory");
        else               asm volatile("cp.async.wait_group 0;" ::: "memory");
        __syncthreads();

        uint32_t smA = sbase + (uint32_t)(c % STAGES) * STG_BYTES;
        uint32_t smB = smA + A_BYTES;

        #pragma unroll
        for (int ks = 0; ks < 4; ks++) {
            uint32_t af[4][4];
            #pragma unroll
            for (int mf = 0; mf < 4; mf++) {
                int row  = warp_m * 64 + mf * 16 + a_row_l;
                int grpk = ks * 2 + a_kg_l;
                uint32_t addr = smA + row * 128 +
                                (((grpk ^ (row & 7)) & 7) << 4);
                ldsm4(af[mf][0], af[mf][1], af[mf][2], af[mf][3], addr);
            }
            uint32_t bf[8][2];
            #pragma unroll
            for (int np = 0; np < 4; np++) {
                int row  = warp_n * 64 + np * 16 + b_row_l;
                int grpk = ks * 2 + b_kg_l;
                uint32_t addr = smB + row * 128 +
                                (((grpk ^ (row & 7)) & 7) << 4);
                uint32_t r0, r1, r2, r3;
                ldsm4(r0, r1, r2, r3, addr);
                bf[np * 2][0]     = r0; bf[np * 2][1]     = r1;
                bf[np * 2 + 1][0] = r2; bf[np * 2 + 1][1] = r3;
            }
            #pragma unroll
            for (int mf = 0; mf < 4; mf++)
                #pragma unroll
                for (int nf = 0; nf < 8; nf++)
                    mma_f16(acc[mf][nf], af[mf], bf[nf]);
        }
        __syncthreads();
    }

    int g = lane >> 2;
    int q = lane & 3;

    float2 bv[8];
    if (EPI != EPI_NONE) {
        #pragma unroll
        for (int nf = 0; nf < 8; nf++) {
            int col = n0 + warp_n * 64 + nf * 8 + q * 2;
            bv[nf] = *reinterpret_cast<const float2*>(&bias[col]);
        }
    }

    #pragma unroll
    for (int mf = 0; mf < 4; mf++) {
        long r0 = m0 + warp_m * 64 + mf * 16 + g;
        long r1 = r0 + 8;
        #pragma unroll
        for (int nf = 0; nf < 8; nf++) {
            int col = n0 + warp_n * 64 + nf * 8 + q * 2;
            float2 v0 = make_float2(acc[mf][nf][0], acc[mf][nf][1]);
            float2 v1 = make_float2(acc[mf][nf][2], acc[mf][nf][3]);
            if (EPI == EPI_NONE) {
                __half* C = (__half*)Cv;
                *reinterpret_cast<__half2*>(&C[r0 * N + col]) =
                    __floats2half2_rn(v0.x, v0.y);
                *reinterpret_cast<__half2*>(&C[r1 * N + col]) =
                    __floats2half2_rn(v1.x, v1.y);
            } else if (EPI == EPI_GELU_BIAS) {
                __half* C = (__half*)Cv;
                *reinterpret_cast<__half2*>(&C[r0 * N + col]) =
                    __floats2half2_rn(gelu_exact(v0.x + bv[nf].x),
                                      gelu_exact(v0.y + bv[nf].y));
                *reinterpret_cast<__half2*>(&C[r1 * N + col]) =
                    __floats2half2_rn(gelu_exact(v1.x + bv[nf].x),
                                      gelu_exact(v1.y + bv[nf].y));
            } else if (EPI == EPI_BIAS_RES) {
                float* C = (float*)Cv;
                float2 e0 = *reinterpret_cast<const float2*>(&res[r0 * N + col]);
                float2 e1 = *reinterpret_cast<const float2*>(&res[r1 * N + col]);
                v0.x += bv[nf].x + e0.x; v0.y += bv[nf].y + e0.y;
                v1.x += bv[nf].x + e1.x; v1.y += bv[nf].y + e1.y;
                *reinterpret_cast<float2*>(&C[r0 * N + col]) = v0;
                *reinterpret_cast<float2*>(&C[r1 * N + col]) = v1;
            } else { // EPI_BIAS_ACC
                float* C = (float*)Cv;
                float2 e0 = *reinterpret_cast<const float2*>(&C[r0 * N + col]);
                float2 e1 = *reinterpret_cast<const float2*>(&C[r1 * N + col]);
                v0.x += bv[nf].x + e0.x; v0.y += bv[nf].y + e0.y;
                v1.x += bv[nf].x + e1.x; v1.y += bv[nf].y + e1.y;
                *reinterpret_cast<float2*>(&C[r0 * N + col]) = v0;
                *reinterpret_cast<float2*>(&C[r1 * N + col]) = v1;
            }
        }
    }
}

// ---------------------------------------------------------------------------
// Tensor-core window attention (r12): 4 heads per 128-thread CTA, 2 CTAs/SM.
// ---------------------------------------------------------------------------
#define AROW_B    768
#define AQKV_B    (WS * AROW_B)
#define POS_PAD   68
#define ATTN_SMEM (AQKV_B + WS * POS_PAD * 4)

__global__ __launch_bounds__(128, 2)
void attn_mma_kernel(const __half* __restrict__ qkv,
                     const float* __restrict__ pos,
                     __half* __restrict__ out)
{
    extern __shared__ char smem[];
    uint32_t sb = smem_u32(smem);
    float* pos_s = reinterpret_cast<float*>(smem + AQKV_B);

    int tid  = threadIdx.x;
    int lane = tid & 31;
    int w    = tid >> 5;
    int win  = blockIdx.x;
    int yh   = blockIdx.y;
    int b    = blockIdx.z;

    #pragma unroll
    for (int it = 0; it < 24; it++) {
        int slot = it * 128 + tid;
        int row  = slot / 48;
        int grp  = slot % 48;
        int sec  = grp >> 4;
        int within = grp & 15;
        int srcgrp = sec * 32 + yh * 16 + within;
        long t = (long)b * NPB + ((win * WS + WS / 2 + row) & (NPB - 1));
        cpa16(sb + row * AROW_B + ((grp ^ (row & 7)) << 4),
              qkv + t * 768 + srcgrp * 8);
    }
    #pragma unroll
    for (int it = 0; it < 8; it++) {
        int slot = it * 128 + tid;
        int row  = slot >> 4;
        int c4   = slot & 15;
        cpa16(sb + AQKV_B + (uint32_t)(row * POS_PAD + c4 * 4) * 4,
              pos + row * 64 + c4 * 4);
    }
    CPA_COMMIT();
    asm volatile("cp.async.wait_group 0;" ::: "memory");
    __syncthreads();

    int g = lane >> 2;
    int q = lane & 3;

    float dots[4][8][4];
    #pragma unroll
    for (int i = 0; i < 4; i++)
        #pragma unroll
        for (int j = 0; j < 8; j++)
            #pragma unroll
            for (int e = 0; e < 4; e++) dots[i][j][e] = 0.f;

    int a_row_l = lane & 15;
    int a_kg_l  = lane >> 4;
    int b_row_l = ((lane >> 4) << 3) + (lane & 7);
    int b_kg_l  = (lane >> 3) & 1;

    #pragma unroll
    for (int ks = 0; ks < 2; ks++) {
        uint32_t af[4][4];
        #pragma unroll
        for (int mf = 0; mf < 4; mf++) {
            int row = mf * 16 + a_row_l;
            int grp = w * 4 + ks * 2 + a_kg_l;
            uint32_t addr = sb + row * AROW_B + ((grp ^ (row & 7)) << 4);
            ldsm4(af[mf][0], af[mf][1], af[mf][2], af[mf][3], addr);
        }
        uint32_t bf[8][2];
        #pragma unroll
        for (int np = 0; np < 4; np++) {
            int row = np * 16 + b_row_l;
            int grp = 16 + w * 4 + ks * 2 + b_kg_l;
            uint32_t addr = sb + row * AROW_B + ((grp ^ (row & 7)) << 4);
            uint32_t r0, r1, r2, r3;
            ldsm4(r0, r1, r2, r3, addr);
            bf[np * 2][0]     = r0; bf[np * 2][1]     = r1;
            bf[np * 2 + 1][0] = r2; bf[np * 2 + 1][1] = r3;
        }
        #pragma unroll
        for (int mf = 0; mf < 4; mf++)
            #pragma unroll
            for (int nf = 0; nf < 8; nf++)
                mma_f16(dots[mf][nf], af[mf], bf[nf]);
    }

    const float scale = 0.17677669529663687f;
    float inv_l[4][2];
    #pragma unroll
    for (int mf = 0; mf < 4; mf++) {
        #pragma unroll
        for (int rp = 0; rp < 2; rp++) {
            int row = mf * 16 + g + rp * 8;
            float m = -1e30f;
            #pragma unroll
            for (int nf = 0; nf < 8; nf++) {
                float2 pp = *reinterpret_cast<const float2*>(
                    &pos_s[row * POS_PAD + nf * 8 + 2 * q]);
                float c0 = dots[mf][nf][rp * 2 + 0] * scale + pp.x;
                float c1 = dots[mf][nf][rp * 2 + 1] * scale + pp.y;
                dots[mf][nf][rp * 2 + 0] = c0;
                dots[mf][nf][rp * 2 + 1] = c1;
                m = fmaxf(m, fmaxf(c0, c1));
            }
            m = fmaxf(m, __shfl_xor_sync(0xffffffffu, m, 1));
            m = fmaxf(m, __shfl_xor_sync(0xffffffffu, m, 2));
            float s = 0.f;
            #pragma unroll
            for (int nf = 0; nf < 8; nf++) {
                float e0 = __expf(dots[mf][nf][rp * 2 + 0] - m);
                float e1 = __expf(dots[mf][nf][rp * 2 + 1] - m);
                dots[mf][nf][rp * 2 + 0] = e0;
                dots[mf][nf][rp * 2 + 1] = e1;
                s += e0 + e1;
            }
            s += __shfl_xor_sync(0xffffffffu, s, 1);
            s += __shfl_xor_sync(0xffffffffu, s, 2);
            inv_l[mf][rp] = 1.f / s;
        }
    }

    uint32_t p[4][4][4];
    #pragma unroll
    for (int mf = 0; mf < 4; mf++)
        #pragma unroll
        for (int ks = 0; ks < 4; ks++) {
            p[mf][ks][0] = packh2(dots[mf][2 * ks][0],     dots[mf][2 * ks][1]);
            p[mf][ks][1] = packh2(dots[mf][2 * ks][2],     dots[mf][2 * ks][3]);
            p[mf][ks][2] = packh2(dots[mf][2 * ks + 1][0], dots[mf][2 * ks + 1][1]);
            p[mf][ks][3] = packh2(dots[mf][2 * ks + 1][2], dots[mf][2 * ks + 1][3]);
        }

    float o[4][4][4];
    #pragma unroll
    for (int i = 0; i < 4; i++)
        #pragma unroll
        for (int j = 0; j < 4; j++)
            #pragma unroll
            for (int e = 0; e < 4; e++) o[i][j][e] = 0.f;

    #pragma unroll
    for (int ks = 0; ks < 4; ks++) {
        uint32_t bb[4][2];
        #pragma unroll
        for (int hf = 0; hf < 2; hf++) {
            int row = ks * 16 + (lane & 15);
            int grp = 32 + w * 4 + 2 * hf + (lane >> 4);
            uint32_t addr = sb + row * AROW_B + ((grp ^ (row & 7)) << 4);
            uint32_t r0, r1, r2, r3;
            ldsm4t(r0, r1, r2, r3, addr);
            bb[2 * hf][0]     = r0; bb[2 * hf][1]     = r1;
            bb[2 * hf + 1][0] = r2; bb[2 * hf + 1][1] = r3;
        }
        #pragma unroll
        for (int mf = 0; mf < 4; mf++)
            #pragma unroll
            for (int nf = 0; nf < 4; nf++)
                mma_f16(o[mf][nf], p[mf][ks], bb[nf]);
    }

    #pragma unroll
    for (int mf = 0; mf < 4; mf++) {
        #pragma unroll
        for (int rp = 0; rp < 2; rp++) {
            int r = mf * 16 + g + rp * 8;
            float il = inv_l[mf][rp];
            #pragma unroll
            for (int nf = 0; nf < 4; nf++) {
                uint32_t addr = sb + r * AROW_B +
                                (((w * 4 + nf) ^ (r & 7)) << 4) + 4 * q;
                uint32_t vv = packh2(o[mf][nf][rp * 2 + 0] * il,
                                     o[mf][nf][rp * 2 + 1] * il);
                asm volatile("st.shared.b32 [%0], %1;" :: "r"(addr), "r"(vv)
                             : "memory");
            }
        }
    }
    __syncthreads();

    #pragma unroll
    for (int it = 0; it < 8; it++) {
        int slot = it * 128 + tid;
        int row  = slot >> 4;
        int gi   = slot & 15;
        uint32_t addr = sb + row * AROW_B + ((gi ^ (row & 7)) << 4);
        uint4 vv;
        asm volatile("ld.shared.v4.b32 {%0,%1,%2,%3}, [%4];"
                     : "=r"(vv.x), "=r"(vv.y), "=r"(vv.z), "=r"(vv.w)
                     : "r"(addr));
        long t = (long)b * NPB + ((win * WS + WS / 2 + row) & (NPB - 1));
        *reinterpret_cast<uint4*>(&out[t * DIMC + yh * 128 + gi * 8]) = vv;
    }
}

// ---------------------------------------------------------------------------
// launch
// ---------------------------------------------------------------------------
extern "C" void kernel_launch(void* const* d_in, const int* in_sizes, int n_in,
                              void* d_out, int out_size)
{
    const float* x      = (const float*)d_in[0];
    const float* w_qkv  = (const float*)d_in[1];
    const float* w_out  = (const float*)d_in[2];
    const float* b_out  = (const float*)d_in[3];
    const float* pos    = (const float*)d_in[4];
    const float* ln1_g  = (const float*)d_in[5];
    const float* ln1_b  = (const float*)d_in[6];
    const float* w1     = (const float*)d_in[7];
    const float* b1     = (const float*)d_in[8];
    const float* w2     = (const float*)d_in[9];
    const float* b2     = (const float*)d_in[10];
    const float* ln2_g  = (const float*)d_in[11];
    const float* ln2_b  = (const float*)d_in[12];
    float* out = (float*)d_out;

    int tokens = in_sizes[0] / DIMC;   // 131072

    __half *p_ln, *p_qkv, *p_attn, *p_h, *p_wqkvT, *p_woutT, *p_w1T, *p_w2T;
    cudaGetSymbolAddress((void**)&p_ln,    g_ln);
    cudaGetSymbolAddress((void**)&p_qkv,   g_qkv);
    cudaGetSymbolAddress((void**)&p_attn,  g_attn);
    cudaGetSymbolAddress((void**)&p_h,     g_h);
    cudaGetSymbolAddress((void**)&p_wqkvT, g_wqkvT);
    cudaGetSymbolAddress((void**)&p_woutT, g_woutT);
    cudaGetSymbolAddress((void**)&p_w1T,   g_w1T);
    cudaGetSymbolAddress((void**)&p_w2T,   g_w2T);

    cudaFuncSetAttribute(hgemm<EPI_NONE>,
        cudaFuncAttributeMaxDynamicSharedMemorySize, GEMM_SMEM_BYTES);
    cudaFuncSetAttribute(hgemm<EPI_BIAS_RES>,
        cudaFuncAttributeMaxDynamicSharedMemorySize, GEMM_SMEM_BYTES);
    cudaFuncSetAttribute(hgemm<EPI_GELU_BIAS>,
        cudaFuncAttributeMaxDynamicSharedMemorySize, GEMM_SMEM_BYTES);
    cudaFuncSetAttribute(hgemm<EPI_BIAS_ACC>,
        cudaFuncAttributeMaxDynamicSharedMemorySize, GEMM_SMEM_BYTES);
    cudaFuncSetAttribute(attn_mma_kernel,
        cudaFuncAttributeMaxDynamicSharedMemorySize, ATTN_SMEM);

    // #1: merged transposes (single launch)
    transpose_all_kernel<<<768, dim3(32, 8)>>>(
        w_qkv, w_out, w1, w2, p_wqkvT, p_woutT, p_w1T, p_w2T);

    // #2: LN1 (warp-per-row)
    ln_kernel<<<tokens / 8, 256>>>(x, ln1_g, ln1_b, p_ln);

    // #3: QKV GEMM
    {
        dim3 grid(768 / BN, tokens / BM);
        hgemm<EPI_NONE><<<grid, GTHR, GEMM_SMEM_BYTES>>>(
            p_ln, p_wqkvT, p_qkv, nullptr, nullptr, tokens, 768, DIMC);
    }

    // #4: attention (ncu capture slot)
    {
        dim3 grid(NPB / WS, 2, tokens / NPB);
        attn_mma_kernel<<<grid, 128, ATTN_SMEM>>>(p_qkv, pos, p_attn);
    }

    // #5: proj + residual (r12 config: BN=128, 2 CTAs/SM)
    {
        dim3 grid(DIMC / BN, tokens / BM);
        hgemm<EPI_BIAS_RES><<<grid, GTHR, GEMM_SMEM_BYTES>>>(
            p_attn, p_woutT, out, b_out, x, tokens, DIMC, DIMC);
    }

    // #6: LN2 (warp-per-row)
    ln_kernel<<<tokens / 8, 256>>>(out, ln2_g, ln2_b, p_ln);

    // #7: MLP1 + GELU
    {
        dim3 grid(MLPD / BN, tokens / BM);
        hgemm<EPI_GELU_BIAS><<<grid, GTHR, GEMM_SMEM_BYTES>>>(
            p_ln, p_w1T, p_h, b1, nullptr, tokens, MLPD, DIMC);
    }

    // #8: MLP2 accumulate
    {
        dim3 grid(DIMC / BN, tokens / BM);
        hgemm<EPI_BIAS_ACC><<<grid, GTHR, GEMM_SMEM_BYTES>>>(
            p_h, p_w2T, out, b2, nullptr, tokens, DIMC, MLPD);
    }
}

// round 16
// speedup vs baseline: 1.0281x; 1.0084x over previous
#include <cuda_runtime.h>
#include <cuda_fp16.h>
#include <math.h>
#include <stdint.h>

// ---------------------------------------------------------------------------
// PointSwinBlock on GB300 (sm_103): fp16 mma.sync GEMMs (at legacy-HMMA
// ceiling) + 2-CTA/SM TC window attention (shift/mask gather) + warp-row LN.
// Round 15 = round 14 + attention index-math cleanup + transpose/LN1 merge.
// B=2, N=65536, DIM=256, HEADS=8, HEAD_DIM=32, WS=64, MLP=1024
// ---------------------------------------------------------------------------

#define DIMC   256
#define NTOK   131072
#define NPB    65536
#define HEADS  8
#define HDIM   32
#define WS     64
#define MLPD   1024

__device__ __half g_ln  [(size_t)NTOK * DIMC];
__device__ __half g_qkv [(size_t)NTOK * 768];
__device__ __half g_attn[(size_t)NTOK * DIMC];
__device__ __half g_h   [(size_t)NTOK * MLPD];
__device__ __half g_wqkvT[768 * DIMC];
__device__ __half g_woutT[DIMC * DIMC];
__device__ __half g_w1T  [MLPD * DIMC];
__device__ __half g_w2T  [DIMC * MLPD];

__device__ __forceinline__ uint32_t smem_u32(const void* p) {
    uint32_t a;
    asm("{ .reg .u64 t; cvta.to.shared.u64 t, %1; cvt.u32.u64 %0, t; }"
        : "=r"(a) : "l"(p));
    return a;
}
__device__ __forceinline__ void cpa16(uint32_t dst, const void* src) {
    asm volatile("cp.async.cg.shared.global [%0], [%1], 16;"
                 :: "r"(dst), "l"(src) : "memory");
}
#define CPA_COMMIT() asm volatile("cp.async.commit_group;" ::: "memory")

__device__ __forceinline__ void ldsm4(uint32_t& r0, uint32_t& r1,
                                      uint32_t& r2, uint32_t& r3,
                                      uint32_t addr) {
    asm volatile("ldmatrix.sync.aligned.m8n8.x4.shared.b16 {%0,%1,%2,%3}, [%4];"
                 : "=r"(r0), "=r"(r1), "=r"(r2), "=r"(r3) : "r"(addr));
}
__device__ __forceinline__ void ldsm4t(uint32_t& r0, uint32_t& r1,
                                       uint32_t& r2, uint32_t& r3,
                                       uint32_t addr) {
    asm volatile("ldmatrix.sync.aligned.m8n8.x4.trans.shared.b16 {%0,%1,%2,%3}, [%4];"
                 : "=r"(r0), "=r"(r1), "=r"(r2), "=r"(r3) : "r"(addr));
}
__device__ __forceinline__ void mma_f16(float* d, const uint32_t* a,
                                        const uint32_t* b) {
    asm volatile(
        "mma.sync.aligned.m16n8k16.row.col.f32.f16.f16.f32 "
        "{%0,%1,%2,%3}, {%4,%5,%6,%7}, {%8,%9}, {%0,%1,%2,%3};"
        : "+f"(d[0]), "+f"(d[1]), "+f"(d[2]), "+f"(d[3])
        : "r"(a[0]), "r"(a[1]), "r"(a[2]), "r"(a[3]),
          "r"(b[0]), "r"(b[1]));
}
__device__ __forceinline__ float gelu_exact(float v)
{
    return 0.5f * v * (1.f + erff(v * 0.7071067811865476f));
}
__device__ __forceinline__ uint32_t packh2(float a, float b) {
    __half2 h = __floats2half2_rn(a, b);
    return *reinterpret_cast<uint32_t*>(&h);
}

// ---------------------------------------------------------------------------
// LayerNorm body: one warp per row (row = global row index).
// ---------------------------------------------------------------------------
__device__ __forceinline__ void ln_row(const float* __restrict__ x,
                                       const float* __restrict__ g,
                                       const float* __restrict__ b,
                                       __half* __restrict__ y,
                                       long row, int lane)
{
    const float* xr = x + row * DIMC;
    float4 v0 = *reinterpret_cast<const float4*>(xr + lane * 4);
    float4 v1 = *reinterpret_cast<const float4*>(xr + 128 + lane * 4);

    float s  = v0.x + v0.y + v0.z + v0.w + v1.x + v1.y + v1.z + v1.w;
    float s2 = v0.x * v0.x + v0.y * v0.y + v0.z * v0.z + v0.w * v0.w +
               v1.x * v1.x + v1.y * v1.y + v1.z * v1.z + v1.w * v1.w;
    #pragma unroll
    for (int o = 16; o; o >>= 1) {
        s  += __shfl_xor_sync(0xffffffffu, s,  o);
        s2 += __shfl_xor_sync(0xffffffffu, s2, o);
    }
    float mu  = s  * (1.f / DIMC);
    float var = s2 * (1.f / DIMC) - mu * mu;
    float inv = rsqrtf(var + 1e-5f);

    float4 g0 = *reinterpret_cast<const float4*>(g + lane * 4);
    float4 b0 = *reinterpret_cast<const float4*>(b + lane * 4);
    float4 g1 = *reinterpret_cast<const float4*>(g + 128 + lane * 4);
    float4 b1 = *reinterpret_cast<const float4*>(b + 128 + lane * 4);

    uint2 o0, o1;
    o0.x = packh2((v0.x - mu) * inv * g0.x + b0.x,
                  (v0.y - mu) * inv * g0.y + b0.y);
    o0.y = packh2((v0.z - mu) * inv * g0.z + b0.z,
                  (v0.w - mu) * inv * g0.w + b0.w);
    o1.x = packh2((v1.x - mu) * inv * g1.x + b1.x,
                  (v1.y - mu) * inv * g1.y + b1.y);
    o1.y = packh2((v1.z - mu) * inv * g1.z + b1.z,
                  (v1.w - mu) * inv * g1.w + b1.w);
    *reinterpret_cast<uint2*>(y + row * DIMC + lane * 4)       = o0;
    *reinterpret_cast<uint2*>(y + row * DIMC + 128 + lane * 4) = o1;
}

__global__ void ln_kernel(const float* __restrict__ x,
                          const float* __restrict__ g,
                          const float* __restrict__ b,
                          __half* __restrict__ y)
{
    ln_row(x, g, b, y, (long)blockIdx.x * 8 + (threadIdx.x >> 5),
           threadIdx.x & 31);
}

// ---------------------------------------------------------------------------
// Combined prologue: blocks [0,768) transpose weights; blocks >=768 do LN1.
// ---------------------------------------------------------------------------
__global__ void prologue_kernel(const float* __restrict__ wqkv,
                                const float* __restrict__ wout,
                                const float* __restrict__ w1,
                                const float* __restrict__ w2,
                                __half* __restrict__ owqkv,
                                __half* __restrict__ owout,
                                __half* __restrict__ ow1,
                                __half* __restrict__ ow2,
                                const float* __restrict__ x,
                                const float* __restrict__ ln_g,
                                const float* __restrict__ ln_b,
                                __half* __restrict__ y)
{
    int bid = blockIdx.x;
    if (bid >= 768) {
        ln_row(x, ln_g, ln_b, y,
               (long)(bid - 768) * 8 + (threadIdx.x >> 5), threadIdx.x & 31);
        return;
    }
    __shared__ float t[32][33];
    int tx = threadIdx.x & 31;
    int ty = threadIdx.x >> 5;
    const float* in; __half* out; int R, C, tx_, ty_;
    if (bid < 192)      { in = wqkv; out = owqkv; R = DIMC; C = 768;
                          tx_ = bid % 24; ty_ = bid / 24; }
    else if (bid < 256) { bid -= 192; in = wout; out = owout; R = DIMC; C = DIMC;
                          tx_ = bid % 8;  ty_ = bid / 8; }
    else if (bid < 512) { bid -= 256; in = w1;   out = ow1;   R = DIMC; C = MLPD;
                          tx_ = bid % 32; ty_ = bid / 32; }
    else                { bid -= 512; in = w2;   out = ow2;   R = MLPD; C = DIMC;
                          tx_ = bid % 8;  ty_ = bid / 8; }
    int bx = tx_ * 32, by = ty_ * 32;
    #pragma unroll
    for (int i = ty; i < 32; i += 8)
        t[i][tx] = in[(long)(by + i) * C + bx + tx];
    __syncthreads();
    #pragma unroll
    for (int i = ty; i < 32; i += 8)
        out[(long)(bx + i) * R + by + tx] = __float2half(t[tx][i]);
}

// ---------------------------------------------------------------------------
// fp16 GEMM (r11/r12 config): 128x128 CTA tile, BK=64h, 4 warps (2x2, 64x64),
// 3-stage cp.async, 96KB smem, 2 CTAs/SM.
// ---------------------------------------------------------------------------
#define EPI_NONE      0
#define EPI_BIAS_RES  1
#define EPI_GELU_BIAS 2
#define EPI_BIAS_ACC  3

#define BM  128
#define BN  128
#define BKH 64
#define A_BYTES   16384
#define STG_BYTES 32768
#define STAGES    3
#define GEMM_SMEM_BYTES (STAGES * STG_BYTES)
#define GTHR 128

template <int EPI>
__global__ __launch_bounds__(GTHR, 2)
void hgemm(const __half* __restrict__ A, const __half* __restrict__ Bt,
           void* __restrict__ Cv,
           const float* __restrict__ bias,
           const float* __restrict__ res,
           int M, int N, int K)
{
    extern __shared__ char smem[];
    uint32_t sbase = smem_u32(smem);

    int  tid    = threadIdx.x;
    int  lane   = tid & 31;
    int  wid    = tid >> 5;
    int  warp_m = wid >> 1;
    int  warp_n = wid & 1;
    long m0     = (long)blockIdx.y * BM;
    int  n0     = blockIdx.x * BN;
    int  nc     = K / BKH;

    int l_row = tid >> 3;
    int l_grp = tid & 7;
    uint32_t l_off = (uint32_t)(l_row * 128 + ((l_grp ^ (l_row & 7)) << 4));

    auto ldgsts = [&](int kc, int st) {
        uint32_t sb = sbase + (uint32_t)st * STG_BYTES + l_off;
        const __half* Ap = A  + (m0 + l_row) * K + kc * BKH + l_grp * 8;
        #pragma unroll
        for (int it = 0; it < 8; it++)
            cpa16(sb + (uint32_t)(it * 16 * 128), Ap + (long)(it * 16) * K);
        const __half* Bp = Bt + ((long)n0 + l_row) * K + kc * BKH + l_grp * 8;
        #pragma unroll
        for (int it = 0; it < 8; it++)
            cpa16(sb + (uint32_t)(A_BYTES + it * 16 * 128),
                  Bp + (long)(it * 16) * K);
        CPA_COMMIT();
    };

    float acc[4][8][4];
    #pragma unroll
    for (int i = 0; i < 4; i++)
        #pragma unroll
        for (int j = 0; j < 8; j++)
            #pragma unroll
            for (int e = 0; e < 4; e++) acc[i][j][e] = 0.f;

    ldgsts(0, 0);
    if (nc > 1) ldgsts(1, 1);

    int a_row_l = (lane & 15);
    int a_kg_l  = (lane >> 4);
    int b_row_l = ((lane >> 4) << 3) + (lane & 7);
    int b_kg_l  = (lane >> 3) & 1;

    for (int c = 0; c < nc; c++) {
        if (c + 2 < nc) ldgsts(c + 2, (c + 2) % STAGES);

        int rem = nc - 1 - c; if (rem > 2) rem = 2;
        if (rem == 2)      asm volatile("cp.async.wait_group 2;" ::: "memory");
        else if (rem == 1) asm volatile("cp.async.wait_group 1;" ::: "memory");
        else               asm volatile("cp.async.wait_group 0;" ::: "memory");
        __syncthreads();

        uint32_t smA = sbase + (uint32_t)(c % STAGES) * STG_BYTES;
        uint32_t smB = smA + A_BYTES;

        #pragma unroll
        for (int ks = 0; ks < 4; ks++) {
            uint32_t af[4][4];
            #pragma unroll
            for (int mf = 0; mf < 4; mf++) {
                int row  = warp_m * 64 + mf * 16 + a_row_l;
                int grpk = ks * 2 + a_kg_l;
                uint32_t addr = smA + row * 128 +
                                (((grpk ^ (row & 7)) & 7) << 4);
                ldsm4(af[mf][0], af[mf][1], af[mf][2], af[mf][3], addr);
            }
            uint32_t bf[8][2];
            #pragma unroll
            for (int np = 0; np < 4; np++) {
                int row  = warp_n * 64 + np * 16 + b_row_l;
                int grpk = ks * 2 + b_kg_l;
                uint32_t addr = smB + row * 128 +
                                (((grpk ^ (row & 7)) & 7) << 4);
                uint32_t r0, r1, r2, r3;
                ldsm4(r0, r1, r2, r3, addr);
                bf[np * 2][0]     = r0; bf[np * 2][1]     = r1;
                bf[np * 2 + 1][0] = r2; bf[np * 2 + 1][1] = r3;
            }
            #pragma unroll
            for (int mf = 0; mf < 4; mf++)
                #pragma unroll
                for (int nf = 0; nf < 8; nf++)
                    mma_f16(acc[mf][nf], af[mf], bf[nf]);
        }
        __syncthreads();
    }

    int g = lane >> 2;
    int q = lane & 3;

    float2 bv[8];
    if (EPI != EPI_NONE) {
        #pragma unroll
        for (int nf = 0; nf < 8; nf++) {
            int col = n0 + warp_n * 64 + nf * 8 + q * 2;
            bv[nf] = *reinterpret_cast<const float2*>(&bias[col]);
        }
    }

    #pragma unroll
    for (int mf = 0; mf < 4; mf++) {
        long r0 = m0 + warp_m * 64 + mf * 16 + g;
        long r1 = r0 + 8;
        #pragma unroll
        for (int nf = 0; nf < 8; nf++) {
            int col = n0 + warp_n * 64 + nf * 8 + q * 2;
            float2 v0 = make_float2(acc[mf][nf][0], acc[mf][nf][1]);
            float2 v1 = make_float2(acc[mf][nf][2], acc[mf][nf][3]);
            if (EPI == EPI_NONE) {
                __half* C = (__half*)Cv;
                *reinterpret_cast<__half2*>(&C[r0 * N + col]) =
                    __floats2half2_rn(v0.x, v0.y);
                *reinterpret_cast<__half2*>(&C[r1 * N + col]) =
                    __floats2half2_rn(v1.x, v1.y);
            } else if (EPI == EPI_GELU_BIAS) {
                __half* C = (__half*)Cv;
                *reinterpret_cast<__half2*>(&C[r0 * N + col]) =
                    __floats2half2_rn(gelu_exact(v0.x + bv[nf].x),
                                      gelu_exact(v0.y + bv[nf].y));
                *reinterpret_cast<__half2*>(&C[r1 * N + col]) =
                    __floats2half2_rn(gelu_exact(v1.x + bv[nf].x),
                                      gelu_exact(v1.y + bv[nf].y));
            } else if (EPI == EPI_BIAS_RES) {
                float* C = (float*)Cv;
                float2 e0 = *reinterpret_cast<const float2*>(&res[r0 * N + col]);
                float2 e1 = *reinterpret_cast<const float2*>(&res[r1 * N + col]);
                v0.x += bv[nf].x + e0.x; v0.y += bv[nf].y + e0.y;
                v1.x += bv[nf].x + e1.x; v1.y += bv[nf].y + e1.y;
                *reinterpret_cast<float2*>(&C[r0 * N + col]) = v0;
                *reinterpret_cast<float2*>(&C[r1 * N + col]) = v1;
            } else { // EPI_BIAS_ACC
                float* C = (float*)Cv;
                float2 e0 = *reinterpret_cast<const float2*>(&C[r0 * N + col]);
                float2 e1 = *reinterpret_cast<const float2*>(&C[r1 * N + col]);
                v0.x += bv[nf].x + e0.x; v0.y += bv[nf].y + e0.y;
                v1.x += bv[nf].x + e1.x; v1.y += bv[nf].y + e1.y;
                *reinterpret_cast<float2*>(&C[r0 * N + col]) = v0;
                *reinterpret_cast<float2*>(&C[r1 * N + col]) = v1;
            }
        }
    }
}

// ---------------------------------------------------------------------------
// Tensor-core window attention: 4 heads per 128-thread CTA, 2 CTAs/SM.
// Gather uses shift/mask indexing only (3 section loops).
// ---------------------------------------------------------------------------
#define AROW_B    768
#define AQKV_B    (WS * AROW_B)
#define POS_PAD   68
#define ATTN_SMEM (AQKV_B + WS * POS_PAD * 4)

__global__ __launch_bounds__(128, 2)
void attn_mma_kernel(const __half* __restrict__ qkv,
                     const float* __restrict__ pos,
                     __half* __restrict__ out)
{
    extern __shared__ char smem[];
    uint32_t sb = smem_u32(smem);
    float* pos_s = reinterpret_cast<float*>(smem + AQKV_B);

    int tid  = threadIdx.x;
    int lane = tid & 31;
    int w    = tid >> 5;
    int win  = blockIdx.x;
    int yh   = blockIdx.y;
    int b    = blockIdx.z;

    long tbase = (long)b * NPB;
    int  rbase = win * WS + WS / 2;

    // gather: 3 sections (q/k/v) x 64 rows x 16 groups, shift/mask only
    {
        int wi0   = tid & 15;               // group-within-section
        int row0  = tid >> 4;               // 0..7 (+8 per it)
        int srcg0 = yh * 16 + wi0;
        #pragma unroll
        for (int sec = 0; sec < 3; sec++) {
            const __half* src0 = qkv + (srcg0 + sec * 32) * 8;
            int grp = sec * 16 + wi0;
            #pragma unroll
            for (int it = 0; it < 8; it++) {
                int row = row0 + it * 8;
                long t  = tbase + ((rbase + row) & (NPB - 1));
                cpa16(sb + row * AROW_B + ((grp ^ (row & 7)) << 4),
                      src0 + t * 768);
            }
        }
    }
    #pragma unroll
    for (int it = 0; it < 8; it++) {
        int slot = it * 128 + tid;
        int row  = slot >> 4;
        int c4   = slot & 15;
        cpa16(sb + AQKV_B + (uint32_t)(row * POS_PAD + c4 * 4) * 4,
              pos + row * 64 + c4 * 4);
    }
    CPA_COMMIT();
    asm volatile("cp.async.wait_group 0;" ::: "memory");
    __syncthreads();

    int g = lane >> 2;
    int q = lane & 3;

    float dots[4][8][4];
    #pragma unroll
    for (int i = 0; i < 4; i++)
        #pragma unroll
        for (int j = 0; j < 8; j++)
            #pragma unroll
            for (int e = 0; e < 4; e++) dots[i][j][e] = 0.f;

    int a_row_l = lane & 15;
    int a_kg_l  = lane >> 4;
    int b_row_l = ((lane >> 4) << 3) + (lane & 7);
    int b_kg_l  = (lane >> 3) & 1;

    #pragma unroll
    for (int ks = 0; ks < 2; ks++) {
        uint32_t af[4][4];
        #pragma unroll
        for (int mf = 0; mf < 4; mf++) {
            int row = mf * 16 + a_row_l;
            int grp = w * 4 + ks * 2 + a_kg_l;
            uint32_t addr = sb + row * AROW_B + ((grp ^ (row & 7)) << 4);
            ldsm4(af[mf][0], af[mf][1], af[mf][2], af[mf][3], addr);
        }
        uint32_t bf[8][2];
        #pragma unroll
        for (int np = 0; np < 4; np++) {
            int row = np * 16 + b_row_l;
            int grp = 16 + w * 4 + ks * 2 + b_kg_l;
            uint32_t addr = sb + row * AROW_B + ((grp ^ (row & 7)) << 4);
            uint32_t r0, r1, r2, r3;
            ldsm4(r0, r1, r2, r3, addr);
            bf[np * 2][0]     = r0; bf[np * 2][1]     = r1;
            bf[np * 2 + 1][0] = r2; bf[np * 2 + 1][1] = r3;
        }
        #pragma unroll
        for (int mf = 0; mf < 4; mf++)
            #pragma unroll
            for (int nf = 0; nf < 8; nf++)
                mma_f16(dots[mf][nf], af[mf], bf[nf]);
    }

    const float scale = 0.17677669529663687f;
    float inv_l[4][2];
    #pragma unroll
    for (int mf = 0; mf < 4; mf++) {
        #pragma unroll
        for (int rp = 0; rp < 2; rp++) {
            int row = mf * 16 + g + rp * 8;
            float m = -1e30f;
            #pragma unroll
            for (int nf = 0; nf < 8; nf++) {
                float2 pp = *reinterpret_cast<const float2*>(
                    &pos_s[row * POS_PAD + nf * 8 + 2 * q]);
                float c0 = dots[mf][nf][rp * 2 + 0] * scale + pp.x;
                float c1 = dots[mf][nf][rp * 2 + 1] * scale + pp.y;
                dots[mf][nf][rp * 2 + 0] = c0;
                dots[mf][nf][rp * 2 + 1] = c1;
                m = fmaxf(m, fmaxf(c0, c1));
            }
            m = fmaxf(m, __shfl_xor_sync(0xffffffffu, m, 1));
            m = fmaxf(m, __shfl_xor_sync(0xffffffffu, m, 2));
            float s = 0.f;
            #pragma unroll
            for (int nf = 0; nf < 8; nf++) {
                float e0 = __expf(dots[mf][nf][rp * 2 + 0] - m);
                float e1 = __expf(dots[mf][nf][rp * 2 + 1] - m);
                dots[mf][nf][rp * 2 + 0] = e0;
                dots[mf][nf][rp * 2 + 1] = e1;
                s += e0 + e1;
            }
            s += __shfl_xor_sync(0xffffffffu, s, 1);
            s += __shfl_xor_sync(0xffffffffu, s, 2);
            inv_l[mf][rp] = 1.f / s;
        }
    }

    uint32_t p[4][4][4];
    #pragma unroll
    for (int mf = 0; mf < 4; mf++)
        #pragma unroll
        for (int ks = 0; ks < 4; ks++) {
            p[mf][ks][0] = packh2(dots[mf][2 * ks][0],     dots[mf][2 * ks][1]);
            p[mf][ks][1] = packh2(dots[mf][2 * ks][2],     dots[mf][2 * ks][3]);
            p[mf][ks][2] = packh2(dots[mf][2 * ks + 1][0], dots[mf][2 * ks + 1][1]);
            p[mf][ks][3] = packh2(dots[mf][2 * ks + 1][2], dots[mf][2 * ks + 1][3]);
        }

    float o[4][4][4];
    #pragma unroll
    for (int i = 0; i < 4; i++)
        #pragma unroll
        for (int j = 0; j < 4; j++)
            #pragma unroll
            for (int e = 0; e < 4; e++) o[i][j][e] = 0.f;

    #pragma unroll
    for (int ks = 0; ks < 4; ks++) {
        uint32_t bb[4][2];
        #pragma unroll
        for (int hf = 0; hf < 2; hf++) {
            int row = ks * 16 + (lane & 15);
            int grp = 32 + w * 4 + 2 * hf + (lane >> 4);
            uint32_t addr = sb + row * AROW_B + ((grp ^ (row & 7)) << 4);
            uint32_t r0, r1, r2, r3;
            ldsm4t(r0, r1, r2, r3, addr);
            bb[2 * hf][0]     = r0; bb[2 * hf][1]     = r1;
            bb[2 * hf + 1][0] = r2; bb[2 * hf + 1][1] = r3;
        }
        #pragma unroll
        for (int mf = 0; mf < 4; mf++)
            #pragma unroll
            for (int nf = 0; nf < 4; nf++)
                mma_f16(o[mf][nf], p[mf][ks], bb[nf]);
    }

    #pragma unroll
    for (int mf = 0; mf < 4; mf++) {
        #pragma unroll
        for (int rp = 0; rp < 2; rp++) {
            int r = mf * 16 + g + rp * 8;
            float il = inv_l[mf][rp];
            #pragma unroll
            for (int nf = 0; nf < 4; nf++) {
                uint32_t addr = sb + r * AROW_B +
                                (((w * 4 + nf) ^ (r & 7)) << 4) + 4 * q;
                uint32_t vv = packh2(o[mf][nf][rp * 2 + 0] * il,
                                     o[mf][nf][rp * 2 + 1] * il);
                asm volatile("st.shared.b32 [%0], %1;" :: "r"(addr), "r"(vv)
                             : "memory");
            }
        }
    }
    __syncthreads();

    #pragma unroll
    for (int it = 0; it < 8; it++) {
        int slot = it * 128 + tid;
        int row  = slot >> 4;
        int gi   = slot & 15;
        uint32_t addr = sb + row * AROW_B + ((gi ^ (row & 7)) << 4);
        uint4 vv;
        asm volatile("ld.shared.v4.b32 {%0,%1,%2,%3}, [%4];"
                     : "=r"(vv.x), "=r"(vv.y), "=r"(vv.z), "=r"(vv.w)
                     : "r"(addr));
        long t = tbase + ((rbase + row) & (NPB - 1));
        *reinterpret_cast<uint4*>(&out[t * DIMC + yh * 128 + gi * 8]) = vv;
    }
}

// ---------------------------------------------------------------------------
// launch
// ---------------------------------------------------------------------------
extern "C" void kernel_launch(void* const* d_in, const int* in_sizes, int n_in,
                              void* d_out, int out_size)
{
    const float* x      = (const float*)d_in[0];
    const float* w_qkv  = (const float*)d_in[1];
    const float* w_out  = (const float*)d_in[2];
    const float* b_out  = (const float*)d_in[3];
    const float* pos    = (const float*)d_in[4];
    const float* ln1_g  = (const float*)d_in[5];
    const float* ln1_b  = (const float*)d_in[6];
    const float* w1     = (const float*)d_in[7];
    const float* b1     = (const float*)d_in[8];
    const float* w2     = (const float*)d_in[9];
    const float* b2     = (const float*)d_in[10];
    const float* ln2_g  = (const float*)d_in[11];
    const float* ln2_b  = (const float*)d_in[12];
    float* out = (float*)d_out;

    int tokens = in_sizes[0] / DIMC;   // 131072

    __half *p_ln, *p_qkv, *p_attn, *p_h, *p_wqkvT, *p_woutT, *p_w1T, *p_w2T;
    cudaGetSymbolAddress((void**)&p_ln,    g_ln);
    cudaGetSymbolAddress((void**)&p_qkv,   g_qkv);
    cudaGetSymbolAddress((void**)&p_attn,  g_attn);
    cudaGetSymbolAddress((void**)&p_h,     g_h);
    cudaGetSymbolAddress((void**)&p_wqkvT, g_wqkvT);
    cudaGetSymbolAddress((void**)&p_woutT, g_woutT);
    cudaGetSymbolAddress((void**)&p_w1T,   g_w1T);
    cudaGetSymbolAddress((void**)&p_w2T,   g_w2T);

    cudaFuncSetAttribute(hgemm<EPI_NONE>,
        cudaFuncAttributeMaxDynamicSharedMemorySize, GEMM_SMEM_BYTES);
    cudaFuncSetAttribute(hgemm<EPI_BIAS_RES>,
        cudaFuncAttributeMaxDynamicSharedMemorySize, GEMM_SMEM_BYTES);
    cudaFuncSetAttribute(hgemm<EPI_GELU_BIAS>,
        cudaFuncAttributeMaxDynamicSharedMemorySize, GEMM_SMEM_BYTES);
    cudaFuncSetAttribute(hgemm<EPI_BIAS_ACC>,
        cudaFuncAttributeMaxDynamicSharedMemorySize, GEMM_SMEM_BYTES);
    cudaFuncSetAttribute(attn_mma_kernel,
        cudaFuncAttributeMaxDynamicSharedMemorySize, ATTN_SMEM);

    // #1: transposes + LN1 in one launch
    prologue_kernel<<<768 + tokens / 8, 256>>>(
        w_qkv, w_out, w1, w2, p_wqkvT, p_woutT, p_w1T, p_w2T,
        x, ln1_g, ln1_b, p_ln);

    // #2: QKV GEMM
    {
        dim3 grid(768 / BN, tokens / BM);
        hgemm<EPI_NONE><<<grid, GTHR, GEMM_SMEM_BYTES>>>(
            p_ln, p_wqkvT, p_qkv, nullptr, nullptr, tokens, 768, DIMC);
    }

    // #3: attention
    {
        dim3 grid(NPB / WS, 2, tokens / NPB);
        attn_mma_kernel<<<grid, 128, ATTN_SMEM>>>(p_qkv, pos, p_attn);
    }

    // #4: proj + residual (ncu capture slot)
    {
        dim3 grid(DIMC / BN, tokens / BM);
        hgemm<EPI_BIAS_RES><<<grid, GTHR, GEMM_SMEM_BYTES>>>(
            p_attn, p_woutT, out, b_out, x, tokens, DIMC, DIMC);
    }

    // #5: LN2 (warp-per-row)
    ln_kernel<<<tokens / 8, 256>>>(out, ln2_g, ln2_b, p_ln);

    // #6: MLP1 + GELU
    {
        dim3 grid(MLPD / BN, tokens / BM);
        hgemm<EPI_GELU_BIAS><<<grid, GTHR, GEMM_SMEM_BYTES>>>(
            p_ln, p_w1T, p_h, b1, nullptr, tokens, MLPD, DIMC);
    }

    // #7: MLP2 accumulate
    {
        dim3 grid(DIMC / BN, tokens / BM);
        hgemm<EPI_BIAS_ACC><<<grid, GTHR, GEMM_SMEM_BYTES>>>(
            p_h, p_w2T, out, b2, nullptr, tokens, DIMC, MLPD);
    }
}